// round 9
// baseline (speedup 1.0000x reference)
#include <cuda_runtime.h>
#include <cuda_fp16.h>

#define N_NODES 100000
#define N_EDGES 1600000
#define D 48
#define D4 (D / 4)

#define T 256
#define ROW_U4 (D / 8)                                   // 6 uint4 per fp16 row
#define XH_U4 (N_NODES * ROW_U4)                         // 600000
#define CZ_TOTAL (3 * XH_U4)                             // convert + zero two aggs
#define CZ_BLOCKS ((CZ_TOTAL + T - 1) / T)
#define GF_BLOCKS ((N_NODES + T - 1) / T)                // 391, one node/thread

// Device scratch (no allocations allowed):
__device__ __half g_xh[N_NODES * D];     // x in fp16 (9.6 MB)
__device__ __half g_agg0[N_NODES * D];   // fp16 accumulator, even edges
__device__ __half g_agg1[N_NODES * D];   // fp16 accumulator, odd edges

// ---------------------------------------------------------------------------
// Kernel 1: convert x -> fp16 AND zero both agg buffers (all streaming).
// ---------------------------------------------------------------------------
__global__ void convert_zero_kernel(const float* __restrict__ x) {
    int i = blockIdx.x * blockDim.x + threadIdx.x;
    if (i >= CZ_TOTAL) return;
    if (i < XH_U4) {
        const float4* xp = (const float4*)x + (size_t)i * 2;
        float4 v0 = xp[0];
        float4 v1 = xp[1];
        __half2 h[4];
        h[0] = __floats2half2_rn(v0.x, v0.y);
        h[1] = __floats2half2_rn(v0.z, v0.w);
        h[2] = __floats2half2_rn(v1.x, v1.y);
        h[3] = __floats2half2_rn(v1.z, v1.w);
        ((uint4*)g_xh)[i] = *(const uint4*)h;
    } else if (i < 2 * XH_U4) {
        ((uint4*)g_agg0)[i - XH_U4] = make_uint4(0u, 0u, 0u, 0u);
    } else {
        ((uint4*)g_agg1)[i - 2 * XH_U4] = make_uint4(0u, 0u, 0u, 0u);
    }
}

// ---------------------------------------------------------------------------
// Kernel 2: COO scatter of raw x rows: agg[dst] += a_e * xh[src].
// 6 lanes per edge, one red.v4.f16x2 (16 B) each -> contiguous 96 B per edge.
// Edge parity selects the accumulator buffer (shorter fp16 chains).
// ---------------------------------------------------------------------------
__global__ void scatter_kernel(const int* __restrict__ src,
                               const int* __restrict__ dst,
                               const float* __restrict__ vals) {
    int tid = blockIdx.x * blockDim.x + threadIdx.x;
    if (tid >= N_EDGES * 6) return;
    int e = tid / 6;
    int c = tid - e * 6;

    int s = __ldg(src + e);
    int d = __ldg(dst + e);
    float a = __ldg(vals + e);

    float4 raw = *(const float4*)(g_xh + (size_t)s * D + c * 8);
    const __half2* h = (const __half2*)&raw;
    unsigned r[4];
#pragma unroll
    for (int t = 0; t < 4; t++) {
        float2 f = __half22float2(h[t]);
        __half2 o = __floats2half2_rn(a * f.x, a * f.y);
        r[t] = *(const unsigned*)&o;
    }

    __half* base = (e & 1) ? g_agg1 : g_agg0;
    __half* p = base + (size_t)d * D + c * 8;
    asm volatile("red.global.add.noftz.v4.f16x2 [%0], {%1, %2, %3, %4};"
                 :: "l"(p), "r"(r[0]), "r"(r[1]), "r"(r[2]), "r"(r[3])
                 : "memory");
}

// ---------------------------------------------------------------------------
// Kernel 3: out[n] = relu( (agg0[n] + agg1[n]) @ w + b ).
// One node per thread; 48 OUTPUT accumulators live in registers, the input
// row is STREAMED through in 8-float chunks so loads interleave with FMAs.
// ---------------------------------------------------------------------------
__global__ void __launch_bounds__(256, 3)
gemm_finalize_kernel(const float* __restrict__ w,
                     const float* __restrict__ b,
                     float* __restrict__ out) {
    __shared__ float ws[D * D];
    __shared__ float bs[D];
    for (int i = threadIdx.x; i < D * D; i += blockDim.x) ws[i] = w[i];
    if (threadIdx.x < D) bs[threadIdx.x] = b[threadIdx.x];
    __syncthreads();

    int node = blockIdx.x * blockDim.x + threadIdx.x;
    if (node >= N_NODES) return;

    const uint4* p0 = (const uint4*)(g_agg0 + (size_t)node * D);
    const uint4* p1 = (const uint4*)(g_agg1 + (size_t)node * D);

    float4 acc[D4];
#pragma unroll
    for (int j = 0; j < D4; j++) acc[j] = make_float4(0.f, 0.f, 0.f, 0.f);

#pragma unroll
    for (int q = 0; q < ROW_U4; q++) {          // stream 8 input columns
        uint4 r0 = p0[q];
        uint4 r1 = p1[q];
        const __half2* h0 = (const __half2*)&r0;
        const __half2* h1 = (const __half2*)&r1;
        float xv[8];
#pragma unroll
        for (int t = 0; t < 4; t++) {
            float2 f0 = __half22float2(h0[t]);
            float2 f1 = __half22float2(h1[t]);
            xv[2 * t]     = f0.x + f1.x;
            xv[2 * t + 1] = f0.y + f1.y;
        }
#pragma unroll
        for (int t = 0; t < 8; t++) {
            int k = q * 8 + t;
            float xk = xv[t];
#pragma unroll
            for (int j4 = 0; j4 < D4; j4++) {
                float4 wr = *(const float4*)(ws + k * D + j4 * 4);
                acc[j4].x = fmaf(xk, wr.x, acc[j4].x);
                acc[j4].y = fmaf(xk, wr.y, acc[j4].y);
                acc[j4].z = fmaf(xk, wr.z, acc[j4].z);
                acc[j4].w = fmaf(xk, wr.w, acc[j4].w);
            }
        }
    }

    float4* op = (float4*)(out + (size_t)node * D);
#pragma unroll
    for (int j4 = 0; j4 < D4; j4++) {
        float4 bb = *(const float4*)(bs + j4 * 4);
        float4 o;
        o.x = fmaxf(acc[j4].x + bb.x, 0.f);
        o.y = fmaxf(acc[j4].y + bb.y, 0.f);
        o.z = fmaxf(acc[j4].z + bb.z, 0.f);
        o.w = fmaxf(acc[j4].w + bb.w, 0.f);
        op[j4] = o;
    }
}

// ---------------------------------------------------------------------------
extern "C" void kernel_launch(void* const* d_in, const int* in_sizes, int n_in,
                              void* d_out, int out_size) {
    const float* x        = (const float*)d_in[0];
    const float* w        = (const float*)d_in[1];
    const float* b        = (const float*)d_in[2];
    const int*   edge_src = (const int*)d_in[3];
    const int*   edge_dst = (const int*)d_in[4];
    const float* adj_vals = (const float*)d_in[5];
    float* out = (float*)d_out;

    // 1) convert x to fp16 + zero both agg buffers (streaming)
    convert_zero_kernel<<<CZ_BLOCKS, T>>>(x);
    // 2) scatter raw x rows: agg[dst] += a_e * xh[src]
    {
        int total = N_EDGES * 6;
        scatter_kernel<<<(total + T - 1) / T, T>>>(edge_src, edge_dst, adj_vals);
    }
    // 3) out = relu((agg0 + agg1) @ w + b)   — GEMM fused into finalize
    gemm_finalize_kernel<<<GF_BLOCKS, T>>>(w, b, out);
}

// round 10
// speedup vs baseline: 1.1318x; 1.1318x over previous
#include <cuda_runtime.h>
#include <cuda_fp16.h>

#define N_NODES 100000
#define N_EDGES 1600000
#define D 48
#define D4 (D / 4)

#define T 256
#define ROW_U4 (D / 8)                                   // 6 uint4 per fp16 row
#define XH_U4 (N_NODES * ROW_U4)                         // 600000
#define CZ_TOTAL (3 * XH_U4)                             // convert + zero two aggs
#define CZ_BLOCKS ((CZ_TOTAL + T - 1) / T)
#define N_TILES (N_NODES / 16)                           // 6250 (exact)
#define MMA_BLOCKS ((N_TILES + 7) / 8)                   // 8 warps per block

// Device scratch (no allocations allowed):
__device__ __half g_xh[N_NODES * D];     // x in fp16 (9.6 MB)
__device__ __half g_agg0[N_NODES * D];   // fp16 accumulator, even edges
__device__ __half g_agg1[N_NODES * D];   // fp16 accumulator, odd edges

// ---------------------------------------------------------------------------
// Kernel 1: convert x -> fp16 AND zero both agg buffers (all streaming).
// ---------------------------------------------------------------------------
__global__ void convert_zero_kernel(const float* __restrict__ x) {
    int i = blockIdx.x * blockDim.x + threadIdx.x;
    if (i >= CZ_TOTAL) return;
    if (i < XH_U4) {
        const float4* xp = (const float4*)x + (size_t)i * 2;
        float4 v0 = xp[0];
        float4 v1 = xp[1];
        __half2 h[4];
        h[0] = __floats2half2_rn(v0.x, v0.y);
        h[1] = __floats2half2_rn(v0.z, v0.w);
        h[2] = __floats2half2_rn(v1.x, v1.y);
        h[3] = __floats2half2_rn(v1.z, v1.w);
        ((uint4*)g_xh)[i] = *(const uint4*)h;
    } else if (i < 2 * XH_U4) {
        ((uint4*)g_agg0)[i - XH_U4] = make_uint4(0u, 0u, 0u, 0u);
    } else {
        ((uint4*)g_agg1)[i - 2 * XH_U4] = make_uint4(0u, 0u, 0u, 0u);
    }
}

// ---------------------------------------------------------------------------
// Kernel 2: COO scatter of raw x rows: agg[dst] += a_e * xh[src].
// 6 lanes per edge, one red.v4.f16x2 (16 B) each -> contiguous 96 B per edge.
// Edge parity selects the accumulator buffer (shorter fp16 chains).
// ---------------------------------------------------------------------------
__global__ void scatter_kernel(const int* __restrict__ src,
                               const int* __restrict__ dst,
                               const float* __restrict__ vals) {
    int tid = blockIdx.x * blockDim.x + threadIdx.x;
    if (tid >= N_EDGES * 6) return;
    int e = tid / 6;
    int c = tid - e * 6;

    int s = __ldg(src + e);
    int d = __ldg(dst + e);
    float a = __ldg(vals + e);

    float4 raw = *(const float4*)(g_xh + (size_t)s * D + c * 8);
    const __half2* h = (const __half2*)&raw;
    unsigned r[4];
#pragma unroll
    for (int t = 0; t < 4; t++) {
        float2 f = __half22float2(h[t]);
        __half2 o = __floats2half2_rn(a * f.x, a * f.y);
        r[t] = *(const unsigned*)&o;
    }

    __half* base = (e & 1) ? g_agg1 : g_agg0;
    __half* p = base + (size_t)d * D + c * 8;
    asm volatile("red.global.add.noftz.v4.f16x2 [%0], {%1, %2, %3, %4};"
                 :: "l"(p), "r"(r[0]), "r"(r[1]), "r"(r[2]), "r"(r[3])
                 : "memory");
}

// ---------------------------------------------------------------------------
// Kernel 3: out = relu((agg0 + agg1) @ w + b) via HMMA m16n8k16.
// One warp per 16-node tile. B-fragments (w in fp16) built once per warp and
// held in registers; A-fragments loaded straight from global (L2-resident).
// Tensor pipe does the math; zero per-tile shared-memory traffic.
// ---------------------------------------------------------------------------
__global__ void __launch_bounds__(256)
mma_finalize_kernel(const float* __restrict__ w,
                    const float* __restrict__ b,
                    float* __restrict__ out) {
    __shared__ float ws[D * D];
    __shared__ float bs[D];
    for (int i = threadIdx.x; i < D * D; i += blockDim.x) ws[i] = w[i];
    if (threadIdx.x < D) bs[threadIdx.x] = b[threadIdx.x];
    __syncthreads();

    int tile = ((blockIdx.x * blockDim.x + threadIdx.x) >> 5);
    int lane = threadIdx.x & 31;
    int gid = lane >> 2;        // group id 0..7
    int tig = lane & 3;         // thread in group 0..3
    if (tile >= N_TILES) return;

    // --- B fragments: w (fp32, smem) -> fp16 regs. b0: k=tig*2,+1; b1: k+8,+9.
    unsigned bf[3][6][2];
#pragma unroll
    for (int kt = 0; kt < 3; kt++) {
#pragma unroll
        for (int nt = 0; nt < 6; nt++) {
            int n  = nt * 8 + gid;
            int k0 = kt * 16 + tig * 2;
            __half2 h0 = __floats2half2_rn(ws[k0 * D + n], ws[(k0 + 1) * D + n]);
            __half2 h1 = __floats2half2_rn(ws[(k0 + 8) * D + n], ws[(k0 + 9) * D + n]);
            bf[kt][nt][0] = *(const unsigned*)&h0;
            bf[kt][nt][1] = *(const unsigned*)&h1;
        }
    }
    // --- bias fragments: cols nt*8 + tig*2, +1
    float2 bias[6];
#pragma unroll
    for (int nt = 0; nt < 6; nt++)
        bias[nt] = *(const float2*)(bs + nt * 8 + tig * 2);

    int node_base = tile * 16;
    const __half* a0p = g_agg0 + (size_t)node_base * D;
    const __half* a1p = g_agg1 + (size_t)node_base * D;

    float acc[6][4];
#pragma unroll
    for (int nt = 0; nt < 6; nt++)
#pragma unroll
        for (int t = 0; t < 4; t++) acc[nt][t] = 0.f;

#pragma unroll
    for (int kt = 0; kt < 3; kt++) {
        // A fragment (row-major 16x16): a0:(r=gid,c=tig*2) a1:(r+8) a2:(c+8) a3:(r+8,c+8)
        int c0 = kt * 16 + tig * 2;
        unsigned a[4];
#pragma unroll
        for (int t = 0; t < 4; t++) {
            int r = gid + ((t & 1) ? 8 : 0);
            int c = c0 + ((t & 2) ? 8 : 0);
            __half2 v0 = *(const __half2*)(a0p + r * D + c);
            __half2 v1 = *(const __half2*)(a1p + r * D + c);
            __half2 s  = __hadd2(v0, v1);
            a[t] = *(const unsigned*)&s;
        }
#pragma unroll
        for (int nt = 0; nt < 6; nt++) {
            asm volatile(
                "mma.sync.aligned.m16n8k16.row.col.f32.f16.f16.f32 "
                "{%0,%1,%2,%3}, {%4,%5,%6,%7}, {%8,%9}, {%0,%1,%2,%3};"
                : "+f"(acc[nt][0]), "+f"(acc[nt][1]),
                  "+f"(acc[nt][2]), "+f"(acc[nt][3])
                : "r"(a[0]), "r"(a[1]), "r"(a[2]), "r"(a[3]),
                  "r"(bf[kt][nt][0]), "r"(bf[kt][nt][1]));
        }
    }

    // --- epilogue: c0,c1 at (row=gid, col=nt*8+tig*2); c2,c3 at row=gid+8.
#pragma unroll
    for (int nt = 0; nt < 6; nt++) {
        int col = nt * 8 + tig * 2;
        float2 v0, v1;
        v0.x = fmaxf(acc[nt][0] + bias[nt].x, 0.f);
        v0.y = fmaxf(acc[nt][1] + bias[nt].y, 0.f);
        v1.x = fmaxf(acc[nt][2] + bias[nt].x, 0.f);
        v1.y = fmaxf(acc[nt][3] + bias[nt].y, 0.f);
        *(float2*)(out + (size_t)(node_base + gid) * D + col)     = v0;
        *(float2*)(out + (size_t)(node_base + gid + 8) * D + col) = v1;
    }
}

// ---------------------------------------------------------------------------
extern "C" void kernel_launch(void* const* d_in, const int* in_sizes, int n_in,
                              void* d_out, int out_size) {
    const float* x        = (const float*)d_in[0];
    const float* w        = (const float*)d_in[1];
    const float* b        = (const float*)d_in[2];
    const int*   edge_src = (const int*)d_in[3];
    const int*   edge_dst = (const int*)d_in[4];
    const float* adj_vals = (const float*)d_in[5];
    float* out = (float*)d_out;

    // 1) convert x to fp16 + zero both agg buffers (streaming)
    convert_zero_kernel<<<CZ_BLOCKS, T>>>(x);
    // 2) scatter raw x rows: agg[dst] += a_e * xh[src]
    {
        int total = N_EDGES * 6;
        scatter_kernel<<<(total + T - 1) / T, T>>>(edge_src, edge_dst, adj_vals);
    }
    // 3) out = relu((agg0 + agg1) @ w + b) on the tensor pipe
    mma_finalize_kernel<<<MMA_BLOCKS, T>>>(w, b, out);
}

// round 11
// speedup vs baseline: 1.1435x; 1.0104x over previous
#include <cuda_runtime.h>
#include <cuda_fp16.h>

#define N_NODES 100000
#define N_EDGES 1600000
#define D 48
#define D4 (D / 4)

#define T 256
#define ROW_U4 (D / 8)                                   // 6 uint4 per fp16 row
#define XH_U4 (N_NODES * ROW_U4)                         // 600000
#define CZ_TOTAL (3 * XH_U4)                             // convert + zero two aggs
#define CZ_PAIRS (CZ_TOTAL / 2)                          // 900000 (2 chunks/thread)
#define CZ_BLOCKS ((CZ_PAIRS + T - 1) / T)
#define N_TILES (N_NODES / 16)                           // 6250 (exact)
#define MMA_BLOCKS 160                                   // 1280 persistent warps
#define MMA_WARPS (MMA_BLOCKS * (T / 32))

// Device scratch (no allocations allowed):
__device__ __half g_xh[N_NODES * D];     // x in fp16 (9.6 MB)
__device__ __half g_agg0[N_NODES * D];   // fp16 accumulator, even edges
__device__ __half g_agg1[N_NODES * D];   // fp16 accumulator, odd edges

// ---------------------------------------------------------------------------
// Kernel 1: convert x -> fp16 AND zero both agg buffers.
// Two consecutive uint4 chunks per thread for memory-level parallelism.
// ---------------------------------------------------------------------------
__global__ void convert_zero_kernel(const float* __restrict__ x) {
    int p = blockIdx.x * blockDim.x + threadIdx.x;
    if (p >= CZ_PAIRS) return;
    int i = 2 * p;                       // first chunk index (region-aligned)
    if (i < XH_U4) {
        const float4* xp = (const float4*)x + (size_t)i * 2;
        float4 v0 = xp[0], v1 = xp[1], v2 = xp[2], v3 = xp[3];
        __half2 h[8];
        h[0] = __floats2half2_rn(v0.x, v0.y);
        h[1] = __floats2half2_rn(v0.z, v0.w);
        h[2] = __floats2half2_rn(v1.x, v1.y);
        h[3] = __floats2half2_rn(v1.z, v1.w);
        h[4] = __floats2half2_rn(v2.x, v2.y);
        h[5] = __floats2half2_rn(v2.z, v2.w);
        h[6] = __floats2half2_rn(v3.x, v3.y);
        h[7] = __floats2half2_rn(v3.z, v3.w);
        ((uint4*)g_xh)[i]     = *(const uint4*)h;
        ((uint4*)g_xh)[i + 1] = *((const uint4*)h + 1);
    } else if (i < 2 * XH_U4) {
        uint4 z = make_uint4(0u, 0u, 0u, 0u);
        ((uint4*)g_agg0)[i - XH_U4]     = z;
        ((uint4*)g_agg0)[i - XH_U4 + 1] = z;
    } else {
        uint4 z = make_uint4(0u, 0u, 0u, 0u);
        ((uint4*)g_agg1)[i - 2 * XH_U4]     = z;
        ((uint4*)g_agg1)[i - 2 * XH_U4 + 1] = z;
    }
}

// ---------------------------------------------------------------------------
// Kernel 2: COO scatter of raw x rows: agg[dst] += a_e * xh[src].
// 6 lanes per edge, one red.v4.f16x2 (16 B) each -> contiguous 96 B per edge.
// Edge parity selects the accumulator buffer (shorter fp16 chains).
// ---------------------------------------------------------------------------
__global__ void scatter_kernel(const int* __restrict__ src,
                               const int* __restrict__ dst,
                               const float* __restrict__ vals) {
    int tid = blockIdx.x * blockDim.x + threadIdx.x;
    if (tid >= N_EDGES * 6) return;
    int e = tid / 6;
    int c = tid - e * 6;

    int s = __ldg(src + e);
    int d = __ldg(dst + e);
    float a = __ldg(vals + e);

    float4 raw = *(const float4*)(g_xh + (size_t)s * D + c * 8);
    const __half2* h = (const __half2*)&raw;
    unsigned r[4];
#pragma unroll
    for (int t = 0; t < 4; t++) {
        float2 f = __half22float2(h[t]);
        __half2 o = __floats2half2_rn(a * f.x, a * f.y);
        r[t] = *(const unsigned*)&o;
    }

    __half* base = (e & 1) ? g_agg1 : g_agg0;
    __half* p = base + (size_t)d * D + c * 8;
    asm volatile("red.global.add.noftz.v4.f16x2 [%0], {%1, %2, %3, %4};"
                 :: "l"(p), "r"(r[0]), "r"(r[1]), "r"(r[2]), "r"(r[3])
                 : "memory");
}

// ---------------------------------------------------------------------------
// Kernel 3: out = relu((agg0 + agg1) @ w + b) via HMMA m16n8k16.
// PERSISTENT warps: B-fragments + bias built once per warp, then ~5 tiles
// of 16 nodes processed per warp (prologue amortized).
// ---------------------------------------------------------------------------
__global__ void __launch_bounds__(256)
mma_finalize_kernel(const float* __restrict__ w,
                    const float* __restrict__ b,
                    float* __restrict__ out) {
    __shared__ float ws[D * D];
    __shared__ float bs[D];
    for (int i = threadIdx.x; i < D * D; i += blockDim.x) ws[i] = w[i];
    if (threadIdx.x < D) bs[threadIdx.x] = b[threadIdx.x];
    __syncthreads();

    int gwarp = ((blockIdx.x * blockDim.x + threadIdx.x) >> 5);
    int lane = threadIdx.x & 31;
    int gid = lane >> 2;        // group id 0..7
    int tig = lane & 3;         // thread in group 0..3

    // --- B fragments: w (fp32, smem) -> fp16 regs. Built ONCE per warp.
    unsigned bf[3][6][2];
#pragma unroll
    for (int kt = 0; kt < 3; kt++) {
#pragma unroll
        for (int nt = 0; nt < 6; nt++) {
            int n  = nt * 8 + gid;
            int k0 = kt * 16 + tig * 2;
            __half2 h0 = __floats2half2_rn(ws[k0 * D + n], ws[(k0 + 1) * D + n]);
            __half2 h1 = __floats2half2_rn(ws[(k0 + 8) * D + n], ws[(k0 + 9) * D + n]);
            bf[kt][nt][0] = *(const unsigned*)&h0;
            bf[kt][nt][1] = *(const unsigned*)&h1;
        }
    }
    float2 bias[6];
#pragma unroll
    for (int nt = 0; nt < 6; nt++)
        bias[nt] = *(const float2*)(bs + nt * 8 + tig * 2);

    // --- tile loop (persistent) ---
    for (int tile = gwarp; tile < N_TILES; tile += MMA_WARPS) {
        int node_base = tile * 16;
        const __half* a0p = g_agg0 + (size_t)node_base * D;
        const __half* a1p = g_agg1 + (size_t)node_base * D;

        float acc[6][4];
#pragma unroll
        for (int nt = 0; nt < 6; nt++)
#pragma unroll
            for (int t = 0; t < 4; t++) acc[nt][t] = 0.f;

#pragma unroll
        for (int kt = 0; kt < 3; kt++) {
            int c0 = kt * 16 + tig * 2;
            unsigned a[4];
#pragma unroll
            for (int t = 0; t < 4; t++) {
                int r = gid + ((t & 1) ? 8 : 0);
                int c = c0 + ((t & 2) ? 8 : 0);
                __half2 v0 = *(const __half2*)(a0p + r * D + c);
                __half2 v1 = *(const __half2*)(a1p + r * D + c);
                __half2 s  = __hadd2(v0, v1);
                a[t] = *(const unsigned*)&s;
            }
#pragma unroll
            for (int nt = 0; nt < 6; nt++) {
                asm volatile(
                    "mma.sync.aligned.m16n8k16.row.col.f32.f16.f16.f32 "
                    "{%0,%1,%2,%3}, {%4,%5,%6,%7}, {%8,%9}, {%0,%1,%2,%3};"
                    : "+f"(acc[nt][0]), "+f"(acc[nt][1]),
                      "+f"(acc[nt][2]), "+f"(acc[nt][3])
                    : "r"(a[0]), "r"(a[1]), "r"(a[2]), "r"(a[3]),
                      "r"(bf[kt][nt][0]), "r"(bf[kt][nt][1]));
            }
        }

#pragma unroll
        for (int nt = 0; nt < 6; nt++) {
            int col = nt * 8 + tig * 2;
            float2 v0, v1;
            v0.x = fmaxf(acc[nt][0] + bias[nt].x, 0.f);
            v0.y = fmaxf(acc[nt][1] + bias[nt].y, 0.f);
            v1.x = fmaxf(acc[nt][2] + bias[nt].x, 0.f);
            v1.y = fmaxf(acc[nt][3] + bias[nt].y, 0.f);
            *(float2*)(out + (size_t)(node_base + gid) * D + col)     = v0;
            *(float2*)(out + (size_t)(node_base + gid + 8) * D + col) = v1;
        }
    }
}

// ---------------------------------------------------------------------------
extern "C" void kernel_launch(void* const* d_in, const int* in_sizes, int n_in,
                              void* d_out, int out_size) {
    const float* x        = (const float*)d_in[0];
    const float* w        = (const float*)d_in[1];
    const float* b        = (const float*)d_in[2];
    const int*   edge_src = (const int*)d_in[3];
    const int*   edge_dst = (const int*)d_in[4];
    const float* adj_vals = (const float*)d_in[5];
    float* out = (float*)d_out;

    // 1) convert x to fp16 + zero both agg buffers (streaming, 2 chunks/thread)
    convert_zero_kernel<<<CZ_BLOCKS, T>>>(x);
    // 2) scatter raw x rows: agg[dst] += a_e * xh[src]
    {
        int total = N_EDGES * 6;
        scatter_kernel<<<(total + T - 1) / T, T>>>(edge_src, edge_dst, adj_vals);
    }
    // 3) out = relu((agg0 + agg1) @ w + b) on the tensor pipe (persistent warps)
    mma_finalize_kernel<<<MMA_BLOCKS, T>>>(w, b, out);
}

// round 12
// speedup vs baseline: 1.1598x; 1.0142x over previous
#include <cuda_runtime.h>
#include <cuda_fp16.h>

#define N_NODES 100000
#define N_EDGES 1600000
#define D 48
#define D4 (D / 4)

#define T 256
#define ROW_U4 (D / 8)                                   // 6 uint4 per fp16 row
#define AGG_U4 (N_NODES * ROW_U4)                        // 600000 per buffer
#define Z_TOTAL (2 * AGG_U4)
#define Z_BLOCKS ((Z_TOTAL + T - 1) / T)
#define N_TILES (N_NODES / 16)                           // 6250 (exact)
#define MMA_BLOCKS 160                                   // 1280 persistent warps
#define MMA_WARPS (MMA_BLOCKS * (T / 32))

// Device scratch (no allocations allowed):
__device__ __half g_agg0[N_NODES * D];   // fp16 accumulator, even edges (9.6 MB)
__device__ __half g_agg1[N_NODES * D];   // fp16 accumulator, odd edges  (9.6 MB)

// ---------------------------------------------------------------------------
// Kernel 1: zero both agg buffers (pure streaming stores).
// ---------------------------------------------------------------------------
__global__ void zero_kernel() {
    int i = blockIdx.x * blockDim.x + threadIdx.x;
    if (i >= Z_TOTAL) return;
    uint4 z = make_uint4(0u, 0u, 0u, 0u);
    if (i < AGG_U4) ((uint4*)g_agg0)[i] = z;
    else            ((uint4*)g_agg1)[i - AGG_U4] = z;
}

// ---------------------------------------------------------------------------
// Kernel 2: COO scatter straight from fp32 x: agg[dst] += a_e * x[src].
// 6 lanes per edge; lane c loads 8 fp32 (32 B, L2-resident), scales, rounds
// to fp16 once, and issues ONE red.v4.f16x2 (16 B) -> contiguous 96 B/edge.
// Edge parity selects the accumulator buffer (shorter fp16 chains).
// ---------------------------------------------------------------------------
__global__ void scatter_kernel(const float* __restrict__ x,
                               const int* __restrict__ src,
                               const int* __restrict__ dst,
                               const float* __restrict__ vals) {
    int tid = blockIdx.x * blockDim.x + threadIdx.x;
    if (tid >= N_EDGES * 6) return;
    int e = tid / 6;
    int c = tid - e * 6;

    int s = __ldg(src + e);
    int d = __ldg(dst + e);
    float a = __ldg(vals + e);

    const float4* xp = (const float4*)(x + (size_t)s * D + c * 8);
    float4 v0 = __ldg(xp);
    float4 v1 = __ldg(xp + 1);

    __half2 h[4];
    h[0] = __floats2half2_rn(a * v0.x, a * v0.y);
    h[1] = __floats2half2_rn(a * v0.z, a * v0.w);
    h[2] = __floats2half2_rn(a * v1.x, a * v1.y);
    h[3] = __floats2half2_rn(a * v1.z, a * v1.w);

    __half* base = (e & 1) ? g_agg1 : g_agg0;
    __half* p = base + (size_t)d * D + c * 8;
    asm volatile("red.global.add.noftz.v4.f16x2 [%0], {%1, %2, %3, %4};"
                 :: "l"(p),
                    "r"(*(const unsigned*)&h[0]), "r"(*(const unsigned*)&h[1]),
                    "r"(*(const unsigned*)&h[2]), "r"(*(const unsigned*)&h[3])
                 : "memory");
}

// ---------------------------------------------------------------------------
// Kernel 3: out = relu((agg0 + agg1) @ w + b) via HMMA m16n8k16.
// Persistent warps: B-fragments + bias built once per warp, ~5 tiles/warp.
// ---------------------------------------------------------------------------
__global__ void __launch_bounds__(256)
mma_finalize_kernel(const float* __restrict__ w,
                    const float* __restrict__ b,
                    float* __restrict__ out) {
    __shared__ float ws[D * D];
    __shared__ float bs[D];
    for (int i = threadIdx.x; i < D * D; i += blockDim.x) ws[i] = w[i];
    if (threadIdx.x < D) bs[threadIdx.x] = b[threadIdx.x];
    __syncthreads();

    int gwarp = ((blockIdx.x * blockDim.x + threadIdx.x) >> 5);
    int lane = threadIdx.x & 31;
    int gid = lane >> 2;        // group id 0..7
    int tig = lane & 3;         // thread in group 0..3

    // --- B fragments: w (fp32, smem) -> fp16 regs. Built ONCE per warp.
    unsigned bf[3][6][2];
#pragma unroll
    for (int kt = 0; kt < 3; kt++) {
#pragma unroll
        for (int nt = 0; nt < 6; nt++) {
            int n  = nt * 8 + gid;
            int k0 = kt * 16 + tig * 2;
            __half2 h0 = __floats2half2_rn(ws[k0 * D + n], ws[(k0 + 1) * D + n]);
            __half2 h1 = __floats2half2_rn(ws[(k0 + 8) * D + n], ws[(k0 + 9) * D + n]);
            bf[kt][nt][0] = *(const unsigned*)&h0;
            bf[kt][nt][1] = *(const unsigned*)&h1;
        }
    }
    float2 bias[6];
#pragma unroll
    for (int nt = 0; nt < 6; nt++)
        bias[nt] = *(const float2*)(bs + nt * 8 + tig * 2);

    // --- tile loop (persistent) ---
    for (int tile = gwarp; tile < N_TILES; tile += MMA_WARPS) {
        int node_base = tile * 16;
        const __half* a0p = g_agg0 + (size_t)node_base * D;
        const __half* a1p = g_agg1 + (size_t)node_base * D;

        float acc[6][4];
#pragma unroll
        for (int nt = 0; nt < 6; nt++)
#pragma unroll
            for (int t = 0; t < 4; t++) acc[nt][t] = 0.f;

#pragma unroll
        for (int kt = 0; kt < 3; kt++) {
            int c0 = kt * 16 + tig * 2;
            unsigned a[4];
#pragma unroll
            for (int t = 0; t < 4; t++) {
                int r = gid + ((t & 1) ? 8 : 0);
                int c = c0 + ((t & 2) ? 8 : 0);
                __half2 v0 = *(const __half2*)(a0p + r * D + c);
                __half2 v1 = *(const __half2*)(a1p + r * D + c);
                __half2 s  = __hadd2(v0, v1);
                a[t] = *(const unsigned*)&s;
            }
#pragma unroll
            for (int nt = 0; nt < 6; nt++) {
                asm volatile(
                    "mma.sync.aligned.m16n8k16.row.col.f32.f16.f16.f32 "
                    "{%0,%1,%2,%3}, {%4,%5,%6,%7}, {%8,%9}, {%0,%1,%2,%3};"
                    : "+f"(acc[nt][0]), "+f"(acc[nt][1]),
                      "+f"(acc[nt][2]), "+f"(acc[nt][3])
                    : "r"(a[0]), "r"(a[1]), "r"(a[2]), "r"(a[3]),
                      "r"(bf[kt][nt][0]), "r"(bf[kt][nt][1]));
            }
        }

#pragma unroll
        for (int nt = 0; nt < 6; nt++) {
            int col = nt * 8 + tig * 2;
            float2 v0, v1;
            v0.x = fmaxf(acc[nt][0] + bias[nt].x, 0.f);
            v0.y = fmaxf(acc[nt][1] + bias[nt].y, 0.f);
            v1.x = fmaxf(acc[nt][2] + bias[nt].x, 0.f);
            v1.y = fmaxf(acc[nt][3] + bias[nt].y, 0.f);
            *(float2*)(out + (size_t)(node_base + gid) * D + col)     = v0;
            *(float2*)(out + (size_t)(node_base + gid + 8) * D + col) = v1;
        }
    }
}

// ---------------------------------------------------------------------------
extern "C" void kernel_launch(void* const* d_in, const int* in_sizes, int n_in,
                              void* d_out, int out_size) {
    const float* x        = (const float*)d_in[0];
    const float* w        = (const float*)d_in[1];
    const float* b        = (const float*)d_in[2];
    const int*   edge_src = (const int*)d_in[3];
    const int*   edge_dst = (const int*)d_in[4];
    const float* adj_vals = (const float*)d_in[5];
    float* out = (float*)d_out;

    // 1) zero both agg buffers
    zero_kernel<<<Z_BLOCKS, T>>>();
    // 2) scatter straight from fp32 x: agg[dst] += a_e * x[src]
    {
        int total = N_EDGES * 6;
        scatter_kernel<<<(total + T - 1) / T, T>>>(x, edge_src, edge_dst, adj_vals);
    }
    // 3) out = relu((agg0 + agg1) @ w + b) on the tensor pipe (persistent warps)
    mma_finalize_kernel<<<MMA_BLOCKS, T>>>(w, b, out);
}